// round 11
// baseline (speedup 1.0000x reference)
#include <cuda_runtime.h>
#include <cuda_bf16.h>
#include <cooperative_groups.h>

namespace cg = cooperative_groups;

#define D    256
#define F    1024
#define NL   4
#define NC   10
#define CS   8
#define TPB  256
#define M    4

// ---- packed fp32x2 helpers (Blackwell 2x fp32) ----
__device__ __forceinline__ void fmax2(unsigned long long& d,
                                      unsigned long long a,
                                      unsigned long long b) {
    asm("fma.rn.f32x2 %0, %1, %2, %0;" : "+l"(d) : "l"(a), "l"(b));
}
__device__ __forceinline__ unsigned long long dup2(float x) {
    unsigned long long r;
    asm("mov.b64 %0, {%1, %1};" : "=l"(r) : "f"(x));
    return r;
}

#define CLU_ARRIVE() asm volatile("barrier.cluster.arrive.aligned;" ::: "memory")
#define CLU_WAIT()   asm volatile("barrier.cluster.wait.aligned;"   ::: "memory")

__device__ __forceinline__ float gelu_tanh(float x) {
    const float c = 0.7978845608028654f;
    float u = c * (x + 0.044715f * x * x * x);
    return 0.5f * x * (1.0f + tanhf(u));
}

__global__ void __launch_bounds__(TPB, 1) __cluster_dims__(CS, 1, 1)
performer_cls_kernel(const int*   __restrict__ xx,
                     const float* __restrict__ emb_tok,
                     const float* __restrict__ emb_pos,
                     const float* __restrict__ ln1_s,
                     const float* __restrict__ ln1_b,
                     const float* __restrict__ wv,
                     const float* __restrict__ wo,
                     const float* __restrict__ bo,
                     const float* __restrict__ ln2_s,
                     const float* __restrict__ ln2_b,
                     const float* __restrict__ w1,
                     const float* __restrict__ b1v,
                     const float* __restrict__ w2,
                     const float* __restrict__ b2v,
                     const float* __restrict__ wcls,
                     const float* __restrict__ bcls,
                     float* __restrict__ out,
                     int N)
{
    __shared__ float  sh_y[M * D];
    __shared__ float  sh_v[M * D];
    __shared__ float  sh_g[M * F];
    __shared__ float  sh_o[M * D];
    __shared__ float  sh_c[M * 128];
    __shared__ float4 ps4[1056];
    __shared__ float  red[80];

    float* psf = (float*)ps4;

    cg::cluster_group cluster = cg::this_cluster();
    const int tid = threadIdx.x;
    const int r   = (int)cluster.block_rank();
    const int b0  = (blockIdx.x >> 3) * M;

    const int c4  = tid & 7;            // A/C: float4-col in 8-group
    const int ks  = tid >> 3;           // A/C: K-slice 0..31
    const int c4b = tid & 31;           // B: float4-col in 32-group
    const int ksb = tid >> 5;           // B: K-slice 0..7
    const int j0  = r * 32;
    const int j0b = r * 128;
    const int rk   = tid >> 5;
    const int lane = tid & 31;

    // ---------- LN (M batches), params passed as regs ----------
    auto layer_norm = [&](const float* hv, float sc, float bi) {
        float s[M], q[M];
        #pragma unroll
        for (int m = 0; m < M; ++m) { s[m] = hv[m]; q[m] = hv[m] * hv[m]; }
        #pragma unroll
        for (int o = 16; o > 0; o >>= 1) {
            #pragma unroll
            for (int m = 0; m < M; ++m) {
                s[m] += __shfl_xor_sync(0xffffffffu, s[m], o);
                q[m] += __shfl_xor_sync(0xffffffffu, q[m], o);
            }
        }
        int wid = tid >> 5;
        if ((tid & 31) == 0) {
            #pragma unroll
            for (int m = 0; m < M; ++m) {
                red[wid * 8 + m]     = s[m];
                red[wid * 8 + 4 + m] = q[m];
            }
        }
        __syncthreads();
        if (tid < 8) {
            float acc = 0.0f;
            #pragma unroll
            for (int w = 0; w < 8; ++w) acc += red[w * 8 + tid];
            red[64 + tid] = acc;
        }
        __syncthreads();
        #pragma unroll
        for (int m = 0; m < M; ++m) {
            float mu  = red[64 + m] * (1.0f / D);
            float var = red[64 + 4 + m] * (1.0f / D) - mu * mu;
            float inv = rsqrtf(var + 1e-5f);
            sh_y[m * D + tid] = (hv[m] - mu) * inv * sc + bi;
        }
        __syncthreads();
    };

    // ---- prefetch 8 float4 rows of a D-wide matrix (A stages: full set) ----
    auto prefA = [&](const float* W, ulonglong2 (&wp)[8]) {
        const ulonglong2* W4 = (const ulonglong2*)W;
        #pragma unroll
        for (int i = 0; i < 8; ++i)
            wp[i] = W4[(ks * 8 + i) * 64 + r * 8 + c4];
    };

    // ---- A-stage matvec using fully prefetched weights ----
    auto matvecA = [&](const float* in, ulonglong2 (&wp)[8]) {
        unsigned long long axy[M], azw[M];
        #pragma unroll
        for (int m = 0; m < M; ++m) { axy[m] = 0ULL; azw[m] = 0ULL; }
        #pragma unroll
        for (int i = 0; i < 8; ++i) {
            int k = ks * 8 + i;
            #pragma unroll
            for (int m = 0; m < M; ++m) {
                unsigned long long yd = dup2(in[m * D + k]);
                fmax2(axy[m], wp[i].x, yd);
                fmax2(azw[m], wp[i].y, yd);
            }
        }
        #pragma unroll
        for (int m = 0; m < M; ++m)
            *(ulonglong2*)(ps4 + ks * 33 + m * 8 + c4) = make_ulonglong2(axy[m], azw[m]);
        __syncthreads();
        if (tid < 128) {
            int m = tid >> 5, col = tid & 31;
            float acc = 0.0f;
            #pragma unroll
            for (int s = 0; s < 32; ++s) acc += psf[s * 132 + m * 32 + col];
            sh_c[m * 32 + col] = acc;
        }
        __syncthreads();
    };

    auto bcastA = [&](float* sym) {
        float* dst = cluster.map_shared_rank(sym, rk);
        #pragma unroll
        for (int m = 0; m < M; ++m)
            dst[m * D + j0 + lane] = sh_c[m * 32 + lane];
    };

    // ---- init ----
    float hv[M];
    #pragma unroll
    for (int m = 0; m < M; ++m) {
        const int tok = xx[(size_t)(b0 + m) * N];
        hv[m] = emb_tok[(size_t)tok * D + tid] + emb_pos[tid];
    }

    ulonglong2 wpA[8];
    prefA(wv, wpA);                       // layer 0 A1 weights
    float l1s = ln1_s[tid], l1b = ln1_b[tid];

    for (int l = 0; l < NL; ++l) {
        // ======== A1: v0 = LN1(h) @ wv ========
        layer_norm(hv, l1s, l1b);
        matvecA(sh_y, wpA);
        bcastA(sh_v);
        CLU_ARRIVE();
        ulonglong2 wpA2[8];
        prefA(wo + (size_t)l * D * D, wpA2);
        float bo_v = bo[l * D + tid];
        CLU_WAIT();

        // ======== A2: o = v0 @ wo ========
        matvecA(sh_v, wpA2);
        bcastA(sh_o);
        CLU_ARRIVE();
        ulonglong2 wpB[8];
        {
            const ulonglong2* W14 = (const ulonglong2*)(w1 + (size_t)l * D * F);
            #pragma unroll
            for (int i = 0; i < 8; ++i)
                wpB[i] = W14[(ksb * 32 + i) * 256 + r * 32 + c4b];
        }
        float l2s = ln2_s[l * D + tid], l2b = ln2_b[l * D + tid];
        float b1_v = b1v[l * F + j0b + (tid & 127)];
        CLU_WAIT();
        #pragma unroll
        for (int m = 0; m < M; ++m)
            hv[m] += sh_o[m * D + tid] + bo_v;

        // ======== B: hidden = gelu(LN2(h) @ w1 + b1) ========
        layer_norm(hv, l2s, l2b);
        {
            const ulonglong2* W14 = (const ulonglong2*)(w1 + (size_t)l * D * F);
            unsigned long long axy[M], azw[M];
            #pragma unroll
            for (int m = 0; m < M; ++m) { axy[m] = 0ULL; azw[m] = 0ULL; }
            #pragma unroll
            for (int i = 0; i < 8; ++i) {
                int k = ksb * 32 + i;
                #pragma unroll
                for (int m = 0; m < M; ++m) {
                    unsigned long long yd = dup2(sh_y[m * D + k]);
                    fmax2(axy[m], wpB[i].x, yd);
                    fmax2(azw[m], wpB[i].y, yd);
                }
            }
            #pragma unroll
            for (int i = 8; i < 32; ++i) {
                int k = ksb * 32 + i;
                ulonglong2 w = W14[k * 256 + r * 32 + c4b];
                #pragma unroll
                for (int m = 0; m < M; ++m) {
                    unsigned long long yd = dup2(sh_y[m * D + k]);
                    fmax2(axy[m], w.x, yd);
                    fmax2(azw[m], w.y, yd);
                }
            }
            #pragma unroll
            for (int m = 0; m < M; ++m)
                *(ulonglong2*)(ps4 + ksb * 128 + m * 32 + c4b) = make_ulonglong2(axy[m], azw[m]);
            __syncthreads();
            #pragma unroll
            for (int t = 0; t < 2; ++t) {
                int o = tid + t * 256;
                int m = o >> 7, col = o & 127;
                float acc = b1_v;
                #pragma unroll
                for (int s = 0; s < 8; ++s) acc += psf[s * 512 + m * 128 + col];
                sh_c[m * 128 + col] = gelu_tanh(acc);
            }
            __syncthreads();
            float* dst = cluster.map_shared_rank(sh_g, rk);
            #pragma unroll
            for (int m = 0; m < M; ++m)
                #pragma unroll
                for (int e = 0; e < 4; ++e)
                    dst[m * F + j0b + e * 32 + lane] = sh_c[m * 128 + e * 32 + lane];
        }
        CLU_ARRIVE();
        ulonglong2 wpC[8];
        {
            const ulonglong2* W24 = (const ulonglong2*)(w2 + (size_t)l * F * D);
            #pragma unroll
            for (int i = 0; i < 8; ++i)
                wpC[i] = W24[(ks * 32 + i) * 64 + r * 8 + c4];
        }
        float b2_v = b2v[l * D + tid];
        CLU_WAIT();

        // ======== C: delta = hidden @ w2 ========
        {
            const ulonglong2* W24 = (const ulonglong2*)(w2 + (size_t)l * F * D);
            unsigned long long axy[M], azw[M];
            #pragma unroll
            for (int m = 0; m < M; ++m) { axy[m] = 0ULL; azw[m] = 0ULL; }
            #pragma unroll
            for (int i = 0; i < 8; ++i) {
                int k = ks * 32 + i;
                #pragma unroll
                for (int m = 0; m < M; ++m) {
                    unsigned long long yd = dup2(sh_g[m * F + k]);
                    fmax2(axy[m], wpC[i].x, yd);
                    fmax2(azw[m], wpC[i].y, yd);
                }
            }
            #pragma unroll
            for (int i = 8; i < 32; ++i) {
                int k = ks * 32 + i;
                ulonglong2 w = W24[k * 64 + r * 8 + c4];
                #pragma unroll
                for (int m = 0; m < M; ++m) {
                    unsigned long long yd = dup2(sh_g[m * F + k]);
                    fmax2(axy[m], w.x, yd);
                    fmax2(azw[m], w.y, yd);
                }
            }
            #pragma unroll
            for (int m = 0; m < M; ++m)
                *(ulonglong2*)(ps4 + ks * 33 + m * 8 + c4) = make_ulonglong2(axy[m], azw[m]);
            __syncthreads();
            if (tid < 128) {
                int m = tid >> 5, col = tid & 31;
                float acc = 0.0f;
                #pragma unroll
                for (int s = 0; s < 32; ++s) acc += psf[s * 132 + m * 32 + col];
                sh_c[m * 32 + col] = acc;
            }
            __syncthreads();
            bcastA(sh_o);
        }
        CLU_ARRIVE();
        {
            int ln = (l + 1 < NL) ? l + 1 : 0;
            prefA(wv + (size_t)ln * D * D, wpA);
            l1s = ln1_s[ln * D + tid];
            l1b = ln1_b[ln * D + tid];
        }
        CLU_WAIT();
        #pragma unroll
        for (int m = 0; m < M; ++m)
            hv[m] += sh_o[m * D + tid] + b2_v;
    }

    // ======== classifier (rank 0) ========
    if (r == 0) {
        #pragma unroll
        for (int m = 0; m < M; ++m) sh_y[m * D + tid] = hv[m];
        __syncthreads();
        if (tid < 160) {
            const int c = tid >> 4;
            const int s = tid & 15;
            #pragma unroll
            for (int m = 0; m < M; ++m) {
                float acc = 0.0f;
                #pragma unroll
                for (int i = 0; i < 16; ++i) {
                    int k = s * 16 + i;
                    acc = fmaf(sh_y[m * D + k], wcls[k * NC + c], acc);
                }
                psf[m * 176 + c * 17 + s] = acc;
            }
        }
        __syncthreads();
        if (tid < NC) {
            #pragma unroll
            for (int m = 0; m < M; ++m) {
                float acc = bcls[tid];
                #pragma unroll
                for (int s = 0; s < 16; ++s) acc += psf[m * 176 + tid * 17 + s];
                out[(size_t)(b0 + m) * NC + tid] = acc;
            }
        }
    }
}

extern "C" void kernel_launch(void* const* d_in, const int* in_sizes, int n_in,
                              void* d_out, int out_size)
{
    const int*   xx      = (const int*)  d_in[0];
    const float* emb_tok = (const float*)d_in[1];
    const float* emb_pos = (const float*)d_in[2];
    const float* ln1_s   = (const float*)d_in[4];
    const float* ln1_b   = (const float*)d_in[5];
    const float* wv      = (const float*)d_in[8];
    const float* wo      = (const float*)d_in[9];
    const float* bo      = (const float*)d_in[10];
    const float* ln2_s   = (const float*)d_in[11];
    const float* ln2_b   = (const float*)d_in[12];
    const float* w1      = (const float*)d_in[13];
    const float* b1v     = (const float*)d_in[14];
    const float* w2      = (const float*)d_in[15];
    const float* b2v     = (const float*)d_in[16];
    const float* wcls    = (const float*)d_in[17];
    const float* bcls    = (const float*)d_in[18];
    float* out = (float*)d_out;

    const int B = out_size / NC;          // 16
    const int N = in_sizes[0] / B;        // 4096
    const int grid = (B / M) * CS;        // 32 blocks = 4 clusters

    performer_cls_kernel<<<grid, TPB>>>(xx, emb_tok, emb_pos, ln1_s, ln1_b,
                                        wv, wo, bo, ln2_s, ln2_b,
                                        w1, b1v, w2, b2v, wcls, bcls, out, N);
}

// round 13
// speedup vs baseline: 1.0231x; 1.0231x over previous
#include <cuda_runtime.h>
#include <cuda_bf16.h>
#include <cooperative_groups.h>

namespace cg = cooperative_groups;

#define D    256
#define F    1024
#define NL   4
#define NC   10
#define CS   8
#define TPB  256
#define M    4      // batch elements per cluster

#define CLU_ARRIVE() asm volatile("barrier.cluster.arrive.aligned;" ::: "memory")
#define CLU_WAIT()   asm volatile("barrier.cluster.wait.aligned;"   ::: "memory")

__device__ __forceinline__ float gelu_tanh(float x) {
    const float c = 0.7978845608028654f;
    float u = c * (x + 0.044715f * x * x * x);
    return 0.5f * x * (1.0f + tanhf(u));
}

__global__ void __launch_bounds__(TPB, 1) __cluster_dims__(CS, 1, 1)
performer_cls_kernel(const int*   __restrict__ xx,
                     const float* __restrict__ emb_tok,
                     const float* __restrict__ emb_pos,
                     const float* __restrict__ ln1_s,
                     const float* __restrict__ ln1_b,
                     const float* __restrict__ wv,
                     const float* __restrict__ wo,
                     const float* __restrict__ bo,
                     const float* __restrict__ ln2_s,
                     const float* __restrict__ ln2_b,
                     const float* __restrict__ w1,
                     const float* __restrict__ b1v,
                     const float* __restrict__ w2,
                     const float* __restrict__ b2v,
                     const float* __restrict__ wcls,
                     const float* __restrict__ bcls,
                     float* __restrict__ out,
                     int N)
{
    __shared__ float  sh_y[M * D];     // LN output
    __shared__ float  sh_v[M * D];     // v0, assembled
    __shared__ float  sh_g[M * F];     // MLP hidden, assembled
    __shared__ float  sh_o[M * D];     // o / mlp-delta, assembled
    __shared__ float  sh_c[M * 128];   // my chunk staging
    __shared__ float4 ps4[1056];       // split-K partials
    __shared__ float  red[80];

    float* psf = (float*)ps4;

    cg::cluster_group cluster = cg::this_cluster();
    const int tid = threadIdx.x;
    const int r   = (int)cluster.block_rank();
    const int b0  = (blockIdx.x >> 3) * M;

    const int c4  = tid & 7;            // A/C: float4-col in 8-group
    const int ks  = tid >> 3;           // A/C: K-slice 0..31
    const int c4b = tid & 31;           // B: float4-col in 32-group
    const int ksb = tid >> 5;           // B: K-slice 0..7
    const int j0  = r * 32;
    const int j0b = r * 128;
    const int rk   = tid >> 5;
    const int lane = tid & 31;

    // ---------- LN (M batches), params as regs ----------
    auto layer_norm = [&](const float* hv, float sc, float bi) {
        float s[M], q[M];
        #pragma unroll
        for (int m = 0; m < M; ++m) { s[m] = hv[m]; q[m] = hv[m] * hv[m]; }
        #pragma unroll
        for (int o = 16; o > 0; o >>= 1) {
            #pragma unroll
            for (int m = 0; m < M; ++m) {
                s[m] += __shfl_xor_sync(0xffffffffu, s[m], o);
                q[m] += __shfl_xor_sync(0xffffffffu, q[m], o);
            }
        }
        int wid = tid >> 5;
        if ((tid & 31) == 0) {
            #pragma unroll
            for (int m = 0; m < M; ++m) {
                red[wid * 8 + m]     = s[m];
                red[wid * 8 + 4 + m] = q[m];
            }
        }
        __syncthreads();
        if (tid < 8) {
            float acc = 0.0f;
            #pragma unroll
            for (int w = 0; w < 8; ++w) acc += red[w * 8 + tid];
            red[64 + tid] = acc;
        }
        __syncthreads();
        #pragma unroll
        for (int m = 0; m < M; ++m) {
            float mu  = red[64 + m] * (1.0f / D);
            float var = red[64 + 4 + m] * (1.0f / D) - mu * mu;
            float inv = rsqrtf(var + 1e-5f);
            sh_y[m * D + tid] = (hv[m] - mu) * inv * sc + bi;
        }
        __syncthreads();
    };

    // ---- prefetch my 8 float4s of a D-wide matrix (A-stage full set) ----
    auto prefA = [&](const float* W, float4 (&wp)[8]) {
        const float4* W4 = (const float4*)W;
        #pragma unroll
        for (int i = 0; i < 8; ++i)
            wp[i] = W4[(ks * 8 + i) * 64 + r * 8 + c4];
    };

    // ---- A-stage matvec on prefetched weights (R8 float4 form) ----
    auto matvecA = [&](const float* in, const float4 (&wp)[8]) {
        float4 a[M];
        #pragma unroll
        for (int m = 0; m < M; ++m) a[m] = make_float4(0.f, 0.f, 0.f, 0.f);
        #pragma unroll
        for (int i = 0; i < 8; ++i) {
            int k = ks * 8 + i;
            float4 w = wp[i];
            #pragma unroll
            for (int m = 0; m < M; ++m) {
                float yk = in[m * D + k];
                a[m].x = fmaf(yk, w.x, a[m].x); a[m].y = fmaf(yk, w.y, a[m].y);
                a[m].z = fmaf(yk, w.z, a[m].z); a[m].w = fmaf(yk, w.w, a[m].w);
            }
        }
        #pragma unroll
        for (int m = 0; m < M; ++m) ps4[ks * 33 + m * 8 + c4] = a[m];
        __syncthreads();
        if (tid < 128) {
            int m = tid >> 5, col = tid & 31;
            float acc = 0.0f;
            #pragma unroll
            for (int s = 0; s < 32; ++s) acc += psf[s * 132 + m * 32 + col];
            sh_c[m * 32 + col] = acc;
        }
        __syncthreads();
    };

    auto bcastA = [&](float* sym) {
        float* dst = cluster.map_shared_rank(sym, rk);
        #pragma unroll
        for (int m = 0; m < M; ++m)
            dst[m * D + j0 + lane] = sh_c[m * 32 + lane];
    };

    // ---- init ----
    float hv[M];
    #pragma unroll
    for (int m = 0; m < M; ++m) {
        const int tok = xx[(size_t)(b0 + m) * N];
        hv[m] = emb_tok[(size_t)tok * D + tid] + emb_pos[tid];
    }

    float4 wpA[8];
    prefA(wv, wpA);                        // layer-0 A1 weights
    float l1s = ln1_s[tid], l1b = ln1_b[tid];

    for (int l = 0; l < NL; ++l) {
        // ======== A1: v0 = LN1(h) @ wv ========
        layer_norm(hv, l1s, l1b);
        matvecA(sh_y, wpA);
        bcastA(sh_v);
        CLU_ARRIVE();
        float4 wpA2[8];
        prefA(wo + (size_t)l * D * D, wpA2);
        float bo_v = bo[l * D + tid];
        CLU_WAIT();

        // ======== A2: o = v0 @ wo ========
        matvecA(sh_v, wpA2);
        bcastA(sh_o);
        CLU_ARRIVE();
        float4 wpB[8];
        {
            const float4* W14 = (const float4*)(w1 + (size_t)l * D * F);
            #pragma unroll
            for (int i = 0; i < 8; ++i)
                wpB[i] = W14[(ksb * 32 + i) * 256 + r * 32 + c4b];
        }
        float l2s = ln2_s[l * D + tid], l2b = ln2_b[l * D + tid];
        float b1_v = b1v[l * F + j0b + (tid & 127)];
        CLU_WAIT();
        #pragma unroll
        for (int m = 0; m < M; ++m)
            hv[m] += sh_o[m * D + tid] + bo_v;

        // ======== B: hidden = gelu(LN2(h) @ w1 + b1) ========
        layer_norm(hv, l2s, l2b);
        {
            const float4* W14 = (const float4*)(w1 + (size_t)l * D * F);
            float4 a[M];
            #pragma unroll
            for (int m = 0; m < M; ++m) a[m] = make_float4(0.f, 0.f, 0.f, 0.f);
            #pragma unroll
            for (int i = 0; i < 8; ++i) {
                int k = ksb * 32 + i;
                float4 w = wpB[i];
                #pragma unroll
                for (int m = 0; m < M; ++m) {
                    float yk = sh_y[m * D + k];
                    a[m].x = fmaf(yk, w.x, a[m].x); a[m].y = fmaf(yk, w.y, a[m].y);
                    a[m].z = fmaf(yk, w.z, a[m].z); a[m].w = fmaf(yk, w.w, a[m].w);
                }
            }
            #pragma unroll
            for (int i = 8; i < 32; ++i) {
                int k = ksb * 32 + i;
                float4 w = W14[k * 256 + r * 32 + c4b];
                #pragma unroll
                for (int m = 0; m < M; ++m) {
                    float yk = sh_y[m * D + k];
                    a[m].x = fmaf(yk, w.x, a[m].x); a[m].y = fmaf(yk, w.y, a[m].y);
                    a[m].z = fmaf(yk, w.z, a[m].z); a[m].w = fmaf(yk, w.w, a[m].w);
                }
            }
            #pragma unroll
            for (int m = 0; m < M; ++m) ps4[ksb * 128 + m * 32 + c4b] = a[m];
            __syncthreads();
            #pragma unroll
            for (int t = 0; t < 2; ++t) {
                int o = tid + t * 256;
                int m = o >> 7, col = o & 127;
                float acc = b1_v;
                #pragma unroll
                for (int s = 0; s < 8; ++s) acc += psf[s * 512 + m * 128 + col];
                sh_c[m * 128 + col] = gelu_tanh(acc);
            }
            __syncthreads();
            float* dst = cluster.map_shared_rank(sh_g, rk);
            #pragma unroll
            for (int m = 0; m < M; ++m)
                #pragma unroll
                for (int e = 0; e < 4; ++e)
                    dst[m * F + j0b + e * 32 + lane] = sh_c[m * 128 + e * 32 + lane];
        }
        CLU_ARRIVE();
        float4 wpC[8];
        {
            const float4* W24 = (const float4*)(w2 + (size_t)l * F * D);
            #pragma unroll
            for (int i = 0; i < 8; ++i)
                wpC[i] = W24[(ks * 32 + i) * 64 + r * 8 + c4];
        }
        float b2_v = b2v[l * D + tid];
        CLU_WAIT();

        // ======== C: delta = hidden @ w2 ========
        {
            const float4* W24 = (const float4*)(w2 + (size_t)l * F * D);
            float4 a[M];
            #pragma unroll
            for (int m = 0; m < M; ++m) a[m] = make_float4(0.f, 0.f, 0.f, 0.f);
            #pragma unroll
            for (int i = 0; i < 8; ++i) {
                int k = ks * 32 + i;
                float4 w = wpC[i];
                #pragma unroll
                for (int m = 0; m < M; ++m) {
                    float yk = sh_g[m * F + k];
                    a[m].x = fmaf(yk, w.x, a[m].x); a[m].y = fmaf(yk, w.y, a[m].y);
                    a[m].z = fmaf(yk, w.z, a[m].z); a[m].w = fmaf(yk, w.w, a[m].w);
                }
            }
            #pragma unroll
            for (int i = 8; i < 32; ++i) {
                int k = ks * 32 + i;
                float4 w = W24[k * 64 + r * 8 + c4];
                #pragma unroll
                for (int m = 0; m < M; ++m) {
                    float yk = sh_g[m * F + k];
                    a[m].x = fmaf(yk, w.x, a[m].x); a[m].y = fmaf(yk, w.y, a[m].y);
                    a[m].z = fmaf(yk, w.z, a[m].z); a[m].w = fmaf(yk, w.w, a[m].w);
                }
            }
            #pragma unroll
            for (int m = 0; m < M; ++m) ps4[ks * 33 + m * 8 + c4] = a[m];
            __syncthreads();
            if (tid < 128) {
                int m = tid >> 5, col = tid & 31;
                float acc = 0.0f;
                #pragma unroll
                for (int s = 0; s < 32; ++s) acc += psf[s * 132 + m * 32 + col];
                sh_c[m * 32 + col] = acc;
            }
            __syncthreads();
            bcastA(sh_o);
        }
        CLU_ARRIVE();
        {
            int ln = (l + 1 < NL) ? l + 1 : 0;
            prefA(wv + (size_t)ln * D * D, wpA);
            l1s = ln1_s[ln * D + tid];
            l1b = ln1_b[ln * D + tid];
        }
        CLU_WAIT();
        #pragma unroll
        for (int m = 0; m < M; ++m)
            hv[m] += sh_o[m * D + tid] + b2_v;
    }

    // ======== classifier (rank 0) ========
    if (r == 0) {
        #pragma unroll
        for (int m = 0; m < M; ++m) sh_y[m * D + tid] = hv[m];
        __syncthreads();
        if (tid < 160) {
            const int c = tid >> 4;
            const int s = tid & 15;
            #pragma unroll
            for (int m = 0; m < M; ++m) {
                float acc = 0.0f;
                #pragma unroll
                for (int i = 0; i < 16; ++i) {
                    int k = s * 16 + i;
                    acc = fmaf(sh_y[m * D + k], wcls[k * NC + c], acc);
                }
                psf[m * 176 + c * 17 + s] = acc;
            }
        }
        __syncthreads();
        if (tid < NC) {
            #pragma unroll
            for (int m = 0; m < M; ++m) {
                float acc = bcls[tid];
                #pragma unroll
                for (int s = 0; s < 16; ++s) acc += psf[m * 176 + tid * 17 + s];
                out[(size_t)(b0 + m) * NC + tid] = acc;
            }
        }
    }
}

extern "C" void kernel_launch(void* const* d_in, const int* in_sizes, int n_in,
                              void* d_out, int out_size)
{
    const int*   xx      = (const int*)  d_in[0];
    const float* emb_tok = (const float*)d_in[1];
    const float* emb_pos = (const float*)d_in[2];
    const float* ln1_s   = (const float*)d_in[4];
    const float* ln1_b   = (const float*)d_in[5];
    const float* wv      = (const float*)d_in[8];
    const float* wo      = (const float*)d_in[9];
    const float* bo      = (const float*)d_in[10];
    const float* ln2_s   = (const float*)d_in[11];
    const float* ln2_b   = (const float*)d_in[12];
    const float* w1      = (const float*)d_in[13];
    const float* b1v     = (const float*)d_in[14];
    const float* w2      = (const float*)d_in[15];
    const float* b2v     = (const float*)d_in[16];
    const float* wcls    = (const float*)d_in[17];
    const float* bcls    = (const float*)d_in[18];
    float* out = (float*)d_out;

    const int B = out_size / NC;          // 16
    const int N = in_sizes[0] / B;        // 4096
    const int grid = (B / M) * CS;        // 32 blocks = 4 clusters

    performer_cls_kernel<<<grid, TPB>>>(xx, emb_tok, emb_pos, ln1_s, ln1_b,
                                        wv, wo, bo, ln2_s, ln2_b,
                                        w1, b1v, w2, b2v, wcls, bcls, out, N);
}

// round 15
// speedup vs baseline: 1.1146x; 1.0894x over previous
#include <cuda_runtime.h>
#include <cuda_bf16.h>
#include <cooperative_groups.h>

namespace cg = cooperative_groups;

#define D    256
#define F    1024
#define NL   4
#define NC   10
#define CS   8
#define TPB  256
#define M    4      // batch elements per cluster

__device__ __forceinline__ float gelu_tanh(float x) {
    const float c = 0.7978845608028654f;
    float u = c * (x + 0.044715f * x * x * x);
    return 0.5f * x * (1.0f + tanhf(u));
}

__global__ void __launch_bounds__(TPB, 1) __cluster_dims__(CS, 1, 1)
performer_cls_kernel(const int*   __restrict__ xx,
                     const float* __restrict__ emb_tok,
                     const float* __restrict__ emb_pos,
                     const float* __restrict__ ln1_s,
                     const float* __restrict__ ln1_b,
                     const float* __restrict__ wv,
                     const float* __restrict__ wo,
                     const float* __restrict__ bo,
                     const float* __restrict__ ln2_s,
                     const float* __restrict__ ln2_b,
                     const float* __restrict__ w1,
                     const float* __restrict__ b1v,
                     const float* __restrict__ w2,
                     const float* __restrict__ b2v,
                     const float* __restrict__ wcls,
                     const float* __restrict__ bcls,
                     float* __restrict__ out,
                     int N)
{
    __shared__ float  sh_y[M * D];        // LN output (local, identical per rank)
    __shared__ float  sh_o[M * D];        // assembled o / mlp-delta (remote bcast)
    __shared__ float  sh_c[M * 128];      // chunk staging (v0 / gelu / assembled)
    __shared__ float  sh_ar[CS * M * 32]; // reduce-scatter slots (remote)
    __shared__ float4 ps4[1056];          // split-K partials
    __shared__ float  red[80];

    float* psf = (float*)ps4;

    cg::cluster_group cluster = cg::this_cluster();
    const int tid = threadIdx.x;
    const int r   = (int)cluster.block_rank();
    const int b0  = (blockIdx.x >> 3) * M;

    const int c4  = tid & 7;            // matvec1-A: float4-col in 8-group (32 cols)
    const int ks  = tid >> 3;           // matvec1-A: K-slice 0..31
    const int c4b = tid & 31;           // matvec1-B: float4-col in 32-group (128 cols)
    const int ksb = tid >> 5;           // matvec1-B: K-slice 0..7
    const int cc  = tid & 63;           // matvec2: float4-col over 256 cols
    const int ss  = tid >> 6;           // matvec2: K-slice 0..3
    const int j0  = r * 32;
    const int j0b = r * 128;
    const int rk   = tid >> 5;          // bcast / scatter target rank
    const int lane = tid & 31;

    // ---------- LN (M batches) ----------
    auto layer_norm = [&](const float* hv, float sc, float bi) {
        float s[M], q[M];
        #pragma unroll
        for (int m = 0; m < M; ++m) { s[m] = hv[m]; q[m] = hv[m] * hv[m]; }
        #pragma unroll
        for (int o = 16; o > 0; o >>= 1) {
            #pragma unroll
            for (int m = 0; m < M; ++m) {
                s[m] += __shfl_xor_sync(0xffffffffu, s[m], o);
                q[m] += __shfl_xor_sync(0xffffffffu, q[m], o);
            }
        }
        int wid = tid >> 5;
        if ((tid & 31) == 0) {
            #pragma unroll
            for (int m = 0; m < M; ++m) {
                red[wid * 8 + m]     = s[m];
                red[wid * 8 + 4 + m] = q[m];
            }
        }
        __syncthreads();
        if (tid < 8) {
            float acc = 0.0f;
            #pragma unroll
            for (int w = 0; w < 8; ++w) acc += red[w * 8 + tid];
            red[64 + tid] = acc;
        }
        __syncthreads();
        #pragma unroll
        for (int m = 0; m < M; ++m) {
            float mu  = red[64 + m] * (1.0f / D);
            float var = red[64 + 4 + m] * (1.0f / D) - mu * mu;
            float inv = rsqrtf(var + 1e-5f);
            sh_y[m * D + tid] = (hv[m] - mu) * inv * sc + bi;
        }
        __syncthreads();
    };

    // ---- 4-slice reduce of full-width partials + reduce-scatter to owners ----
    auto reduce_scatter = [&]() {
        float po[M];
        #pragma unroll
        for (int m = 0; m < M; ++m) {
            float acc = psf[m * 1056 + tid];
            #pragma unroll
            for (int s = 1; s < 4; ++s) acc += psf[m * 1056 + s * 264 + tid];
            po[m] = acc;
        }
        float* dst = cluster.map_shared_rank(sh_ar, rk);
        #pragma unroll
        for (int m = 0; m < M; ++m)
            dst[r * 128 + m * 32 + lane] = po[m];
    };

    // ---- tiny stage: assemble my chunk (+bias) and broadcast to all ranks ----
    auto assemble_bcast = [&](const float* bias) {
        if (tid < 128) {
            int m = tid >> 5, c = tid & 31;
            float acc = bias[j0 + c];
            #pragma unroll
            for (int r2 = 0; r2 < CS; ++r2) acc += sh_ar[r2 * 128 + m * 32 + c];
            sh_c[m * 32 + c] = acc;
        }
        __syncthreads();
        float* dst = cluster.map_shared_rank(sh_o, rk);
        #pragma unroll
        for (int m = 0; m < M; ++m)
            dst[m * D + j0 + lane] = sh_c[m * 32 + lane];
    };

    // ---- init ----
    float hv[M];
    #pragma unroll
    for (int m = 0; m < M; ++m) {
        const int tok = xx[(size_t)(b0 + m) * N];
        hv[m] = emb_tok[(size_t)tok * D + tid] + emb_pos[tid];
    }

    for (int l = 0; l < NL; ++l) {
        // ================== heavy stage A: attention pair ==================
        layer_norm(hv, ln1_s[l * D + tid], ln1_b[l * D + tid]);
        {
            // (1) v0 chunk = y @ wv[:, j0:j0+32]
            const float4* W4 = (const float4*)(wv + (size_t)l * D * D);
            float4 a[M];
            #pragma unroll
            for (int m = 0; m < M; ++m) a[m] = make_float4(0.f, 0.f, 0.f, 0.f);
            #pragma unroll
            for (int i = 0; i < 8; ++i) {
                int k = ks * 8 + i;
                float4 w = W4[k * 64 + r * 8 + c4];
                #pragma unroll
                for (int m = 0; m < M; ++m) {
                    float yk = sh_y[m * D + k];
                    a[m].x = fmaf(yk, w.x, a[m].x); a[m].y = fmaf(yk, w.y, a[m].y);
                    a[m].z = fmaf(yk, w.z, a[m].z); a[m].w = fmaf(yk, w.w, a[m].w);
                }
            }
            #pragma unroll
            for (int m = 0; m < M; ++m) ps4[ks * 33 + m * 8 + c4] = a[m];
            __syncthreads();
            if (tid < 128) {
                int m = tid >> 5, col = tid & 31;
                float acc = 0.0f;
                #pragma unroll
                for (int s = 0; s < 32; ++s) acc += psf[s * 132 + m * 32 + col];
                sh_c[m * 32 + col] = acc;
            }
            __syncthreads();

            // (2) partial o (all 256 cols) from my v0 chunk rows of wo
            const float4* Wo4 = (const float4*)(wo + (size_t)l * D * D);
            float4 pa[M];
            #pragma unroll
            for (int m = 0; m < M; ++m) pa[m] = make_float4(0.f, 0.f, 0.f, 0.f);
            #pragma unroll
            for (int i = 0; i < 8; ++i) {
                int row = j0 + ss * 8 + i;
                float4 w = Wo4[row * 64 + cc];
                #pragma unroll
                for (int m = 0; m < M; ++m) {
                    float yk = sh_c[m * 32 + ss * 8 + i];
                    pa[m].x = fmaf(yk, w.x, pa[m].x); pa[m].y = fmaf(yk, w.y, pa[m].y);
                    pa[m].z = fmaf(yk, w.z, pa[m].z); pa[m].w = fmaf(yk, w.w, pa[m].w);
                }
            }
            #pragma unroll
            for (int m = 0; m < M; ++m) ps4[m * 264 + ss * 66 + cc] = pa[m];
            __syncthreads();
            reduce_scatter();
        }
        cluster.sync();
        assemble_bcast(bo + l * D);
        cluster.sync();
        #pragma unroll
        for (int m = 0; m < M; ++m) hv[m] += sh_o[m * D + tid];

        // ================== heavy stage B: MLP pair ==================
        layer_norm(hv, ln2_s[l * D + tid], ln2_b[l * D + tid]);
        {
            // (1) g chunk = gelu(y @ w1[:, j0b:j0b+128] + b1)
            const float4* W14 = (const float4*)(w1 + (size_t)l * D * F);
            float4 a[M];
            #pragma unroll
            for (int m = 0; m < M; ++m) a[m] = make_float4(0.f, 0.f, 0.f, 0.f);
            #pragma unroll
            for (int i = 0; i < 32; ++i) {
                int k = ksb * 32 + i;
                float4 w = W14[k * 256 + r * 32 + c4b];
                #pragma unroll
                for (int m = 0; m < M; ++m) {
                    float yk = sh_y[m * D + k];
                    a[m].x = fmaf(yk, w.x, a[m].x); a[m].y = fmaf(yk, w.y, a[m].y);
                    a[m].z = fmaf(yk, w.z, a[m].z); a[m].w = fmaf(yk, w.w, a[m].w);
                }
            }
            #pragma unroll
            for (int m = 0; m < M; ++m) ps4[ksb * 128 + m * 32 + c4b] = a[m];
            __syncthreads();
            #pragma unroll
            for (int t = 0; t < 2; ++t) {
                int o = tid + t * 256;
                int m = o >> 7, col = o & 127;
                float acc = b1v[l * F + j0b + col];
                #pragma unroll
                for (int s = 0; s < 8; ++s) acc += psf[s * 512 + m * 128 + col];
                sh_c[m * 128 + col] = gelu_tanh(acc);
            }
            __syncthreads();

            // (2) partial delta (all 256 cols) from my g chunk rows of w2
            const float4* W24 = (const float4*)(w2 + (size_t)l * F * D);
            float4 pa[M];
            #pragma unroll
            for (int m = 0; m < M; ++m) pa[m] = make_float4(0.f, 0.f, 0.f, 0.f);
            #pragma unroll
            for (int i = 0; i < 32; ++i) {
                int row = j0b + ss * 32 + i;
                float4 w = W24[row * 64 + cc];
                #pragma unroll
                for (int m = 0; m < M; ++m) {
                    float yk = sh_c[m * 128 + ss * 32 + i];
                    pa[m].x = fmaf(yk, w.x, pa[m].x); pa[m].y = fmaf(yk, w.y, pa[m].y);
                    pa[m].z = fmaf(yk, w.z, pa[m].z); pa[m].w = fmaf(yk, w.w, pa[m].w);
                }
            }
            #pragma unroll
            for (int m = 0; m < M; ++m) ps4[m * 264 + ss * 66 + cc] = pa[m];
            __syncthreads();
            reduce_scatter();
        }
        cluster.sync();
        assemble_bcast(b2v + l * D);
        cluster.sync();
        #pragma unroll
        for (int m = 0; m < M; ++m) hv[m] += sh_o[m * D + tid];
    }

    // ================== classifier (rank 0) ==================
    if (r == 0) {
        #pragma unroll
        for (int m = 0; m < M; ++m) sh_y[m * D + tid] = hv[m];
        __syncthreads();
        if (tid < 160) {
            const int c = tid >> 4;
            const int s = tid & 15;
            #pragma unroll
            for (int m = 0; m < M; ++m) {
                float acc = 0.0f;
                #pragma unroll
                for (int i = 0; i < 16; ++i) {
                    int k = s * 16 + i;
                    acc = fmaf(sh_y[m * D + k], wcls[k * NC + c], acc);
                }
                psf[m * 176 + c * 17 + s] = acc;
            }
        }
        __syncthreads();
        if (tid < NC) {
            #pragma unroll
            for (int m = 0; m < M; ++m) {
                float acc = bcls[tid];
                #pragma unroll
                for (int s = 0; s < 16; ++s) acc += psf[m * 176 + tid * 17 + s];
                out[(size_t)(b0 + m) * NC + tid] = acc;
            }
        }
    }
}

extern "C" void kernel_launch(void* const* d_in, const int* in_sizes, int n_in,
                              void* d_out, int out_size)
{
    const int*   xx      = (const int*)  d_in[0];
    const float* emb_tok = (const float*)d_in[1];
    const float* emb_pos = (const float*)d_in[2];
    const float* ln1_s   = (const float*)d_in[4];
    const float* ln1_b   = (const float*)d_in[5];
    const float* wv      = (const float*)d_in[8];
    const float* wo      = (const float*)d_in[9];
    const float* bo      = (const float*)d_in[10];
    const float* ln2_s   = (const float*)d_in[11];
    const float* ln2_b   = (const float*)d_in[12];
    const float* w1      = (const float*)d_in[13];
    const float* b1v     = (const float*)d_in[14];
    const float* w2      = (const float*)d_in[15];
    const float* b2v     = (const float*)d_in[16];
    const float* wcls    = (const float*)d_in[17];
    const float* bcls    = (const float*)d_in[18];
    float* out = (float*)d_out;

    const int B = out_size / NC;          // 16
    const int N = in_sizes[0] / B;        // 4096
    const int grid = (B / M) * CS;        // 32 blocks = 4 clusters

    performer_cls_kernel<<<grid, TPB>>>(xx, emb_tok, emb_pos, ln1_s, ln1_b,
                                        wv, wo, bo, ln2_s, ln2_b,
                                        w1, b1v, w2, b2v, wcls, bcls, out, N);
}